// round 2
// baseline (speedup 1.0000x reference)
#include <cuda_runtime.h>
#include <math.h>

#define TT 512
#define BB 32
#define VV 1296
#define LL 64
#define NROWS (TT*BB)

// Scratch (no allocations allowed in kernel_launch)
__device__ int   g_targets[NROWS];
__device__ float g_ce[NROWS];

// ---------------------------------------------------------------------------
// Kernel 1: per-batch forced-alignment DP + backtrack.
// Uses RAW seq_pred values (log-softmax constant per column cancels in the
// strict comparison, so choices are identical to the reference).
// One block per batch. Warp 0 runs the DP with 2 label-rows per lane.
// ---------------------------------------------------------------------------
__global__ void __launch_bounds__(512) dp_align_kernel(
    const float* __restrict__ seq_pred,
    const int*   __restrict__ label,
    const int*   __restrict__ x_len,
    const int*   __restrict__ label_len)
{
    extern __shared__ float smem[];
    float*    pb   = smem;                         // LL*TT floats (gathered band)
    unsigned* chlo = (unsigned*)(pb + LL * TT);    // TT words: choice bits rows even
    unsigned* chhi = chlo + TT;                    // TT words: choice bits rows odd
    __shared__ int labs[LL];

    const int b   = blockIdx.x;
    const int tid = threadIdx.x;
    const int R   = label_len[b];
    const int C   = x_len[b];
    const float ninf = __int_as_float(0xff800000);

    if (tid < LL) labs[tid] = label[b * LL + tid];
    chlo[tid] = 0u;      // blockDim == TT == 512
    chhi[tid] = 0u;
    __syncthreads();

    // Stage gathered band pb[j][i] = seq_pred[j, b, label[i]] (band-masked).
    // Columns j >= C are never touched by DP or backtrack.
    const int total = C * LL;
    for (int idx = tid; idx < total; idx += 512) {
        const int j = idx >> 6;
        const int i = idx & 63;
        float v = ninf;
        if (i < R && j >= i && j <= C - R + i)
            v = __ldg(&seq_pred[(size_t)(j * BB + b) * VV + labs[i]]);
        pb[j * LL + i] = v;
    }
    __syncthreads();

    // Forward DP: lane l owns rows 2l (lo) and 2l+1 (hi).
    if (tid < 32) {
        const int l = tid;
        float dp_lo = (l == 0) ? pb[0] : ninf;     // dp0[i] = i==0 ? pb[0,0] : -inf
        float dp_hi = ninf;
        const float2* pb2 = (const float2*)pb;
        for (int j = 1; j < C; ++j) {
            const float2 p = pb2[j * 32 + l];
            float prev_hi = __shfl_up_sync(0xffffffffu, dp_hi, 1);
            if (l == 0) prev_hi = ninf;
            const bool c_lo = prev_hi > dp_lo;     // strict, matches reference
            const bool c_hi = dp_lo  > dp_hi;
            const unsigned blo = __ballot_sync(0xffffffffu, c_lo);
            const unsigned bhi = __ballot_sync(0xffffffffu, c_hi);
            const float nlo = (c_lo ? prev_hi : dp_lo) + p.x;
            const float nhi = (c_hi ? dp_lo  : dp_hi) + p.y;
            if (l == 0) { chlo[j] = blo; chhi[j] = bhi; }
            dp_lo = nlo; dp_hi = nhi;
        }
    }
    __syncthreads();

    // Padding columns j >= C emit target 0.
    for (int j = C + tid; j < TT; j += 512)
        g_targets[j * BB + b] = 0;

    // Serial backtrack (choice words indexed by fixed j -> prefetchable).
    if (tid == 0) {
        int row = R - 1;
        #pragma unroll 4
        for (int j = C - 1; j >= 0; --j) {
            g_targets[j * BB + b] = labs[row];
            const unsigned w = (row & 1) ? chhi[j] : chlo[j];
            row -= (int)((w >> (row >> 1)) & 1u);
        }
    }
}

// ---------------------------------------------------------------------------
// Block reduction helper (256 threads, 8 warps)
// ---------------------------------------------------------------------------
__device__ __forceinline__ float blk_red(float v, int op_max, float* sred)
{
    #pragma unroll
    for (int o = 16; o; o >>= 1) {
        const float u = __shfl_xor_sync(0xffffffffu, v, o);
        v = op_max ? fmaxf(v, u) : v + u;
    }
    const int w = threadIdx.x >> 5, l = threadIdx.x & 31;
    if (l == 0) sred[w] = v;
    __syncthreads();
    if (threadIdx.x < 8) {
        float x = sred[threadIdx.x];
        #pragma unroll
        for (int o = 4; o; o >>= 1) {
            const float u = __shfl_xor_sync(0xffu, x, o);
            x = op_max ? fmaxf(x, u) : x + u;
        }
        if (threadIdx.x == 0) sred[0] = x;
    }
    __syncthreads();
    const float r = sred[0];
    __syncthreads();
    return r;
}

// ---------------------------------------------------------------------------
// Kernel 2: one block per (t,b) row. Single read of each 1296-wide row into
// registers (float4), softmax stats, analytic smoothed-CE. Masked rows skip
// all heavy loads.
//   ce = smooth*(V*lse_p - sum_p) - (conf - smooth)*(pred[tgt] - lse_p)
// ---------------------------------------------------------------------------
__global__ void __launch_bounds__(256) ce_row_kernel(
    const float* __restrict__ pred,
    const float* __restrict__ seq_pred,
    const int*   __restrict__ x_len)
{
    const int row = blockIdx.x;          // row = t*BB + b (memory-contiguous)
    const int b   = row & (BB - 1);
    const int t   = row >> 5;
    const int tid = threadIdx.x;

    if (t >= x_len[b]) {                 // masked: contributes 0, skip 10KB read
        if (tid == 0) g_ce[row] = 0.0f;
        return;
    }

    const float ninf = __int_as_float(0xff800000);
    const size_t base = (size_t)row * VV;
    const float4* sp4 = (const float4*)(seq_pred + base);
    const float4* p4  = (const float4*)(pred + base);

    const bool has2 = tid < (VV / 4 - 256);   // 324 float4s per row
    const float4 f_ninf = make_float4(ninf, ninf, ninf, ninf);
    const float4 s0 = sp4[tid];
    const float4 s1 = has2 ? sp4[tid + 256] : f_ninf;
    const float4 q0 = p4[tid];
    const float4 q1 = has2 ? p4[tid + 256] : f_ninf;

    __shared__ float sred[8];

    // --- seq_pred: logsumexp ---
    float ms = fmaxf(fmaxf(s0.x, s0.y), fmaxf(s0.z, s0.w));
    ms = fmaxf(ms, fmaxf(fmaxf(s1.x, s1.y), fmaxf(s1.z, s1.w)));
    const float Ms = blk_red(ms, 1, sred);

    float se = expf(s0.x - Ms) + expf(s0.y - Ms) + expf(s0.z - Ms) + expf(s0.w - Ms)
             + expf(s1.x - Ms) + expf(s1.y - Ms) + expf(s1.z - Ms) + expf(s1.w - Ms);
    const float Ss = blk_red(se, 0, sred);

    // --- pred: logsumexp + raw sum ---
    float mp = fmaxf(fmaxf(q0.x, q0.y), fmaxf(q0.z, q0.w));
    mp = fmaxf(mp, fmaxf(fmaxf(q1.x, q1.y), fmaxf(q1.z, q1.w)));
    const float Mp = blk_red(mp, 1, sred);

    float pe = expf(q0.x - Mp) + expf(q0.y - Mp) + expf(q0.z - Mp) + expf(q0.w - Mp)
             + expf(q1.x - Mp) + expf(q1.y - Mp) + expf(q1.z - Mp) + expf(q1.w - Mp);
    const float Sp = blk_red(pe, 0, sred);

    float sl = q0.x + q0.y + q0.z + q0.w;
    if (has2) sl += q1.x + q1.y + q1.z + q1.w;
    const float SumP = blk_red(sl, 0, sred);

    if (tid == 0) {
        const int tgt = g_targets[row];
        const float sp_t = __ldg(&seq_pred[base + tgt]);
        const float p_t  = __ldg(&pred[base + tgt]);
        const float lse_s = Ms + logf(Ss);
        const float lse_p = Mp + logf(Sp);
        const float conf = expf(sp_t - lse_s);
        const float smooth = (1.0f - conf) * (1.0f / (float)(VV - 1));
        g_ce[row] = smooth * ((float)VV * lse_p - SumP)
                  - (conf - smooth) * (p_t - lse_p);
    }
}

// ---------------------------------------------------------------------------
// Kernel 3: deterministic final mean (double accumulation).
// ---------------------------------------------------------------------------
__global__ void __launch_bounds__(512) finalize_kernel(float* __restrict__ out)
{
    double s = 0.0;
    for (int i = threadIdx.x; i < NROWS; i += 512)
        s += (double)g_ce[i];
    #pragma unroll
    for (int o = 16; o; o >>= 1)
        s += __shfl_xor_sync(0xffffffffu, s, o);
    __shared__ double sm[16];
    const int w = threadIdx.x >> 5, l = threadIdx.x & 31;
    if (l == 0) sm[w] = s;
    __syncthreads();
    if (w == 0) {
        double x = (l < 16) ? sm[l] : 0.0;
        #pragma unroll
        for (int o = 8; o; o >>= 1)
            x += __shfl_xor_sync(0xffffffffu, x, o);
        if (l == 0) out[0] = (float)(x / (double)NROWS);
    }
}

// ---------------------------------------------------------------------------
extern "C" void kernel_launch(void* const* d_in, const int* in_sizes, int n_in,
                              void* d_out, int out_size)
{
    const float* pred      = (const float*)d_in[0];
    const float* seq_pred  = (const float*)d_in[1];
    const int*   label     = (const int*)d_in[2];
    const int*   x_len     = (const int*)d_in[3];
    const int*   label_len = (const int*)d_in[4];

    const size_t smem = (size_t)LL * TT * sizeof(float) + 2 * TT * sizeof(unsigned);
    cudaFuncSetAttribute(dp_align_kernel,
                         cudaFuncAttributeMaxDynamicSharedMemorySize, (int)smem);

    dp_align_kernel<<<BB, 512, smem>>>(seq_pred, label, x_len, label_len);
    ce_row_kernel<<<NROWS, 256>>>(pred, seq_pred, x_len);
    finalize_kernel<<<1, 512>>>((float*)d_out);
}